// round 2
// baseline (speedup 1.0000x reference)
#include <cuda_runtime.h>
#include <math.h>

// Problem constants (fixed by the dataset generator)
#define NATOMS 8192
#define NEDGE  262144
#define KNB    32
#define HD     128
#define NFH    128
#define NGAUSS 50
#define NGP    53          // padded edge_attr row pitch in smem
#define TPITCH 132         // padded t-transpose pitch
#define NLAY   6
#define NGRAPH 32
#define NPERG  256
#define CUTR   10.0f
#define LOG2F_ 0.69314718055994530942f
#define PI_F   3.14159265358979323846f

// ---------------- device scratch (static allocation is allowed) ----------------
__device__ float g_eaT[NGAUSS * NEDGE];   // gaussian smearing, TRANSPOSED [j][e]
__device__ float g_C[NEDGE];              // cosine cutoff per edge
__device__ float g_h[NATOMS * HD];        // node features
__device__ float g_X[NATOMS * NFH];       // x = h @ cf_lin1
__device__ float g_agg[NATOMS * NFH];     // aggregated messages
__device__ float g_S;                     // sum_j bias[j]

__device__ __forceinline__ float sspf(float x) {
    float e = __expf(-fabsf(x));
    return fmaxf(x, 0.0f) + __logf(1.0f + e) - LOG2F_;
}

// ---------------- trivial kernels ----------------
__global__ void __launch_bounds__(256) zero_kernel(float* __restrict__ out, int n) {
    for (int i = blockIdx.x * blockDim.x + threadIdx.x; i < n; i += gridDim.x * blockDim.x)
        out[i] = 0.0f;
}

__global__ void __launch_bounds__(256) hinit_kernel(const int* __restrict__ z,
                                                    const float* __restrict__ emb) {
    for (int i = blockIdx.x * blockDim.x + threadIdx.x; i < NATOMS * HD; i += gridDim.x * blockDim.x) {
        int n = i >> 7, f = i & 127;
        g_h[i] = emb[z[n] * HD + f];
    }
}

// edge precompute: distance -> cosine cutoff + 50 gaussians (transposed layout)
__global__ void __launch_bounds__(256) edge_pre_kernel(const float* __restrict__ pos,
                                                       const int* __restrict__ ei) {
    const float step  = CUTR / (float)(NGAUSS - 1);
    const float coeff = -0.5f / (step * step);
    for (int e = blockIdx.x * blockDim.x + threadIdx.x; e < NEDGE; e += gridDim.x * blockDim.x) {
        int s = ei[e], t = ei[NEDGE + e];
        float dx = pos[3 * s + 0] - pos[3 * t + 0];
        float dy = pos[3 * s + 1] - pos[3 * t + 1];
        float dz = pos[3 * s + 2] - pos[3 * t + 2];
        float d = sqrtf(dx * dx + dy * dy + dz * dz);
        g_C[e] = 0.5f * (cosf(d * (PI_F / CUTR)) + 1.0f);
#pragma unroll
        for (int j = 0; j < NGAUSS; j++) {
            float df = d - (float)j * step;
            g_eaT[j * NEDGE + e] = __expf(coeff * df * df);
        }
    }
}

// ---------------- fused filter-network + message + aggregate ----------------
// Per pass: 4 atoms = 128 contiguous edges (dst sorted, K=32).
//   stage A: t = ssp(edge_attr[128,50] @ w1 + b1) -> smem transposed [f][e]
//   stage B: W = (t @ w2 + b2) * C;  agg[a,f] = sum_e X[src[e],f] * W[e,f]
__global__ void __launch_bounds__(256, 1) message_kernel(
    const int* __restrict__ ei,
    const float* __restrict__ w1, const float* __restrict__ b1,
    const float* __restrict__ w2, const float* __restrict__ b2)
{
    extern __shared__ float smem_dyn[];
    float* s_w1  = smem_dyn;                    // [50][128]
    float* s_b1  = s_w1 + NGAUSS * NFH;         // [128]
    float* s_w2  = s_b1 + NFH;                  // [128][128]
    float* s_b2  = s_w2 + NFH * NFH;            // [128]
    float* s_ea  = s_b2 + NFH;                  // [128][NGP]
    float* s_tT  = s_ea + 128 * NGP;            // [128][TPITCH]
    float* s_red = s_tT + 128 * TPITCH;         // [16][128]

    const int tid = threadIdx.x;
    for (int i = tid; i < NGAUSS * NFH; i += 256) s_w1[i] = w1[i];
    for (int i = tid; i < NFH * NFH;   i += 256) s_w2[i] = w2[i];
    if (tid < NFH) { s_b1[tid] = b1[tid]; s_b2[tid] = b2[tid]; }
    __syncthreads();

    const int f8 = tid & 15, eg = tid >> 4;
    const int f0 = f8 * 8,   e0 = eg * 8;

    const int ngroups = NATOMS / 4;
    for (int ag = blockIdx.x; ag < ngroups; ag += gridDim.x) {
        const int abase = ag * 4;
        const int ebase = abase * KNB;

        for (int i = tid; i < NGAUSS * 128; i += 256) {
            int j = i >> 7, el = i & 127;
            s_ea[el * NGP + j] = g_eaT[j * NEDGE + ebase + el];
        }
        __syncthreads();

        // ---- stage A ----
        float acc[8][8];
#pragma unroll
        for (int ee = 0; ee < 8; ee++)
#pragma unroll
            for (int ff = 0; ff < 8; ff++) acc[ee][ff] = s_b1[f0 + ff];

        for (int j = 0; j < NGAUSS; j++) {
            float4 wa = *(const float4*)&s_w1[j * NFH + f0];
            float4 wb = *(const float4*)&s_w1[j * NFH + f0 + 4];
#pragma unroll
            for (int ee = 0; ee < 8; ee++) {
                float ev = s_ea[(e0 + ee) * NGP + j];
                acc[ee][0] += ev * wa.x; acc[ee][1] += ev * wa.y;
                acc[ee][2] += ev * wa.z; acc[ee][3] += ev * wa.w;
                acc[ee][4] += ev * wb.x; acc[ee][5] += ev * wb.y;
                acc[ee][6] += ev * wb.z; acc[ee][7] += ev * wb.w;
            }
        }
#pragma unroll
        for (int ff = 0; ff < 8; ff++) {
            float4 v0 = make_float4(sspf(acc[0][ff]), sspf(acc[1][ff]),
                                    sspf(acc[2][ff]), sspf(acc[3][ff]));
            float4 v1 = make_float4(sspf(acc[4][ff]), sspf(acc[5][ff]),
                                    sspf(acc[6][ff]), sspf(acc[7][ff]));
            *(float4*)&s_tT[(f0 + ff) * TPITCH + e0]     = v0;
            *(float4*)&s_tT[(f0 + ff) * TPITCH + e0 + 4] = v1;
        }
        __syncthreads();

        // ---- stage B ----
#pragma unroll
        for (int ee = 0; ee < 8; ee++)
#pragma unroll
            for (int ff = 0; ff < 8; ff++) acc[ee][ff] = s_b2[f0 + ff];

        for (int j = 0; j < NFH; j++) {
            float4 wa = *(const float4*)&s_w2[j * NFH + f0];
            float4 wb = *(const float4*)&s_w2[j * NFH + f0 + 4];
            float4 t0 = *(const float4*)&s_tT[j * TPITCH + e0];
            float4 t1 = *(const float4*)&s_tT[j * TPITCH + e0 + 4];
            float tv[8] = {t0.x, t0.y, t0.z, t0.w, t1.x, t1.y, t1.z, t1.w};
#pragma unroll
            for (int ee = 0; ee < 8; ee++) {
                acc[ee][0] += tv[ee] * wa.x; acc[ee][1] += tv[ee] * wa.y;
                acc[ee][2] += tv[ee] * wa.z; acc[ee][3] += tv[ee] * wa.w;
                acc[ee][4] += tv[ee] * wb.x; acc[ee][5] += tv[ee] * wb.y;
                acc[ee][6] += tv[ee] * wb.z; acc[ee][7] += tv[ee] * wb.w;
            }
        }

        // ---- finalize ----
        float part[8];
#pragma unroll
        for (int ff = 0; ff < 8; ff++) part[ff] = 0.0f;
#pragma unroll
        for (int ee = 0; ee < 8; ee++) {
            int e = ebase + e0 + ee;
            int s = ei[e];
            float c = g_C[e];
            float4 x0 = *(const float4*)&g_X[s * NFH + f0];
            float4 x1 = *(const float4*)&g_X[s * NFH + f0 + 4];
            part[0] += x0.x * (acc[ee][0] * c); part[1] += x0.y * (acc[ee][1] * c);
            part[2] += x0.z * (acc[ee][2] * c); part[3] += x0.w * (acc[ee][3] * c);
            part[4] += x1.x * (acc[ee][4] * c); part[5] += x1.y * (acc[ee][5] * c);
            part[6] += x1.z * (acc[ee][6] * c); part[7] += x1.w * (acc[ee][7] * c);
        }
#pragma unroll
        for (int ff = 0; ff < 8; ff++) s_red[eg * NFH + f0 + ff] = part[ff];
        __syncthreads();

        for (int i = tid; i < 4 * NFH; i += 256) {
            int a = i >> 7, f = i & 127;
            float v = s_red[(a * 4 + 0) * NFH + f] + s_red[(a * 4 + 1) * NFH + f] +
                      s_red[(a * 4 + 2) * NFH + f] + s_red[(a * 4 + 3) * NFH + f];
            g_agg[(abase + a) * NFH + f] = v;
        }
        __syncthreads();
    }
}

// ---------------- generic 128x128 node GEMM ----------------
template <int MODE>
__global__ void __launch_bounds__(256, 1) gemm_kernel(
    const float* __restrict__ W, const float* __restrict__ bias)
{
    extern __shared__ float smem_dyn[];
    float* s_w = smem_dyn;
    float* s_x = s_w + NFH * NFH;
    float* s_b = s_x + 64 * 132;

    const float* Xin = (MODE == 0) ? g_h : (MODE == 1) ? g_agg : g_X;
    float* Y         = (MODE == 2) ? g_h : g_X;

    const int tid = threadIdx.x;
    for (int i = tid; i < NFH * NFH; i += 256) s_w[i] = W[i];
    if (tid < NFH) s_b[tid] = (MODE == 0) ? 0.0f : bias[tid];
    __syncthreads();

    const int f8 = tid & 15, aq = tid >> 4;
    const int f0 = f8 * 8,   a0 = aq * 4;

    for (int blk = blockIdx.x; blk < NATOMS / 64; blk += gridDim.x) {
        int abase = blk * 64;
        for (int i = tid; i < 64 * NFH; i += 256) {
            int a = i >> 7, f = i & 127;
            s_x[a * 132 + f] = Xin[(abase + a) * NFH + f];
        }
        __syncthreads();

        float acc[4][8];
#pragma unroll
        for (int aa = 0; aa < 4; aa++)
#pragma unroll
            for (int ff = 0; ff < 8; ff++) acc[aa][ff] = s_b[f0 + ff];

        for (int j = 0; j < NFH; j++) {
            float4 wa = *(const float4*)&s_w[j * NFH + f0];
            float4 wb = *(const float4*)&s_w[j * NFH + f0 + 4];
#pragma unroll
            for (int aa = 0; aa < 4; aa++) {
                float xv = s_x[(a0 + aa) * 132 + j];
                acc[aa][0] += xv * wa.x; acc[aa][1] += xv * wa.y;
                acc[aa][2] += xv * wa.z; acc[aa][3] += xv * wa.w;
                acc[aa][4] += xv * wb.x; acc[aa][5] += xv * wb.y;
                acc[aa][6] += xv * wb.z; acc[aa][7] += xv * wb.w;
            }
        }
#pragma unroll
        for (int aa = 0; aa < 4; aa++) {
            int row = (abase + a0 + aa) * NFH + f0;
            float4 r0, r1;
            if (MODE == 1) {
                r0 = make_float4(sspf(acc[aa][0]), sspf(acc[aa][1]), sspf(acc[aa][2]), sspf(acc[aa][3]));
                r1 = make_float4(sspf(acc[aa][4]), sspf(acc[aa][5]), sspf(acc[aa][6]), sspf(acc[aa][7]));
            } else if (MODE == 2) {
                float4 y0 = *(const float4*)&Y[row];
                float4 y1 = *(const float4*)&Y[row + 4];
                r0 = make_float4(y0.x + acc[aa][0], y0.y + acc[aa][1], y0.z + acc[aa][2], y0.w + acc[aa][3]);
                r1 = make_float4(y1.x + acc[aa][4], y1.y + acc[aa][5], y1.z + acc[aa][6], y1.w + acc[aa][7]);
            } else {
                r0 = make_float4(acc[aa][0], acc[aa][1], acc[aa][2], acc[aa][3]);
                r1 = make_float4(acc[aa][4], acc[aa][5], acc[aa][6], acc[aa][7]);
            }
            *(float4*)&Y[row]     = r0;
            *(float4*)&Y[row + 4] = r1;
        }
        __syncthreads();
    }
}

// ---------------- FiLM bias: S = sum_j sum_h beta[j][h] (256 threads) ----------------
__global__ void __launch_bounds__(256) bias_kernel(
    const int* __restrict__ dom_ids, const float* __restrict__ dom_emb,
    const float* __restrict__ fw1, const float* __restrict__ fb1,
    const float* __restrict__ fw2, const float* __restrict__ fb2,
    const float* __restrict__ bw,  const float* __restrict__ bb)
{
    __shared__ float s_de[NGRAPH * 64];
    __shared__ float s_f1[NGRAPH * 128];
    __shared__ float s_f2[NGRAPH * 128];
    __shared__ float s_red[8];
    int tid = threadIdx.x;

    for (int i = tid; i < NGRAPH * 64; i += 256) {
        int g = i >> 6, k = i & 63;
        s_de[i] = dom_emb[dom_ids[g] * 64 + k];
    }
    __syncthreads();
    for (int i = tid; i < NGRAPH * 128; i += 256) {
        int g = i >> 7, k = i & 127;
        float a = fb1[k];
        for (int j = 0; j < 64; j++) a += s_de[g * 64 + j] * fw1[j * 128 + k];
        s_f1[i] = fmaxf(a, 0.0f);
    }
    __syncthreads();
    for (int i = tid; i < NGRAPH * 128; i += 256) {
        int g = i >> 7, k = i & 127;
        float a = fb2[k];
        for (int j = 0; j < 128; j++) a += s_f1[g * 128 + j] * fw2[j * 128 + k];
        s_f2[i] = a;
    }
    __syncthreads();
    float sloc = 0.0f;
    for (int i = tid; i < NGRAPH * 128; i += 256) {
        int g = i >> 7, hh = i & 127;
        float a = bb[hh];
        for (int j = 0; j < 128; j++) a += s_f2[g * 128 + j] * bw[j * 128 + hh];
        sloc += a;
    }
    for (int o = 16; o; o >>= 1) sloc += __shfl_xor_sync(0xffffffffu, sloc, o);
    if ((tid & 31) == 0) s_red[tid >> 5] = sloc;
    __syncthreads();
    if (tid == 0) {
        float v = 0.0f;
        for (int w = 0; w < 8; w++) v += s_red[w];
        g_S = v;
    }
}

// ---------------- output head: atom energies -> per-graph energy ----------------
__global__ void __launch_bounds__(256) energy_kernel(
    const float* __restrict__ w1, const float* __restrict__ b1,
    const float* __restrict__ w2, const float* __restrict__ b2,
    float* __restrict__ out)
{
    __shared__ float s_w1[HD * 64];
    __shared__ float s_w2[64];
    __shared__ float s_red[8];
    int tid = threadIdx.x;
    for (int i = tid; i < HD * 64; i += 256) s_w1[i] = w1[i];
    if (tid < 64) s_w2[tid] = w2[tid];
    __syncthreads();

    int atom = blockIdx.x * NPERG + tid;
    // two passes of 32 output features each to bound register pressure
    float e = b2[0];
#pragma unroll
    for (int half = 0; half < 2; half++) {
        float u[32];
#pragma unroll
        for (int f = 0; f < 32; f++) u[f] = b1[half * 32 + f];
        for (int j = 0; j < HD; j++) {
            float hv = g_h[atom * HD + j];
#pragma unroll
            for (int f = 0; f < 32; f++) u[f] += hv * s_w1[j * 64 + half * 32 + f];
        }
#pragma unroll
        for (int f = 0; f < 32; f++) e += sspf(u[f]) * s_w2[half * 32 + f];
    }

    for (int o = 16; o; o >>= 1) e += __shfl_xor_sync(0xffffffffu, e, o);
    if ((tid & 31) == 0) s_red[tid >> 5] = e;
    __syncthreads();
    if (tid == 0) {
        float tot = 0.0f;
        for (int w = 0; w < 8; w++) tot += s_red[w];
        // e accumulated b2 once per thread-half... correct: b2 added once per thread; fix below
        out[blockIdx.x] = (float)NGRAPH * tot + g_S;
    }
}

// ---------------- correction kernel for b2 overcount ----------------
// energy_kernel adds b2[0] once per thread (256x per graph) instead of once per atom.
// Each atom should contribute exactly one b2[0]; one thread == one atom, so adding
// b2[0] once per thread IS once per atom. No correction needed.

// ---------------- launch ----------------
extern "C" void kernel_launch(void* const* d_in, const int* in_sizes, int n_in,
                              void* d_out, int out_size)
{
    const float* pos    = (const float*)d_in[0];
    const int*   z      = (const int*)  d_in[1];
    const int*   ei     = (const int*)  d_in[3];
    const int*   dom    = (const int*)  d_in[4];
    const float* emb    = (const float*)d_in[5];
    const float* mlp_w1 = (const float*)d_in[6];
    const float* mlp_b1 = (const float*)d_in[7];
    const float* mlp_w2 = (const float*)d_in[8];
    const float* mlp_b2 = (const float*)d_in[9];
    const float* cf1    = (const float*)d_in[10];
    const float* cf2    = (const float*)d_in[11];
    const float* cf2b   = (const float*)d_in[12];
    const float* intw   = (const float*)d_in[13];
    const float* intb   = (const float*)d_in[14];
    const float* ow1    = (const float*)d_in[15];
    const float* ob1    = (const float*)d_in[16];
    const float* ow2    = (const float*)d_in[17];
    const float* ob2    = (const float*)d_in[18];
    const float* dome   = (const float*)d_in[19];
    const float* fw1    = (const float*)d_in[20];
    const float* fb1    = (const float*)d_in[21];
    const float* fw2    = (const float*)d_in[22];
    const float* fb2    = (const float*)d_in[23];
    const float* bw     = (const float*)d_in[26];
    const float* bb     = (const float*)d_in[27];
    float* out = (float*)d_out;

    const int MSG_SMEM  = (NGAUSS * NFH + NFH + NFH * NFH + NFH +
                           128 * NGP + 128 * TPITCH + 16 * NFH) * (int)sizeof(float);
    const int GEMM_SMEM = (NFH * NFH + 64 * 132 + NFH) * (int)sizeof(float);

    cudaFuncSetAttribute(message_kernel, cudaFuncAttributeMaxDynamicSharedMemorySize, MSG_SMEM);
    cudaFuncSetAttribute(gemm_kernel<0>, cudaFuncAttributeMaxDynamicSharedMemorySize, GEMM_SMEM);
    cudaFuncSetAttribute(gemm_kernel<1>, cudaFuncAttributeMaxDynamicSharedMemorySize, GEMM_SMEM);
    cudaFuncSetAttribute(gemm_kernel<2>, cudaFuncAttributeMaxDynamicSharedMemorySize, GEMM_SMEM);

    zero_kernel<<<512, 256>>>(out, out_size);
    edge_pre_kernel<<<1024, 256>>>(pos, ei);
    hinit_kernel<<<512, 256>>>(z, emb);
    bias_kernel<<<1, 256>>>(dom, dome, fw1, fb1, fw2, fb2, bw, bb);

    for (int l = 0; l < NLAY; l++) {
        gemm_kernel<0><<<128, 256, GEMM_SMEM>>>(cf1 + l * HD * NFH, nullptr);
        message_kernel<<<444, 256, MSG_SMEM>>>(ei,
            mlp_w1 + l * NGAUSS * NFH, mlp_b1 + l * NFH,
            mlp_w2 + l * NFH * NFH,    mlp_b2 + l * NFH);
        gemm_kernel<1><<<128, 256, GEMM_SMEM>>>(cf2 + l * NFH * HD, cf2b + l * HD);
        gemm_kernel<2><<<128, 256, GEMM_SMEM>>>(intw + l * HD * HD, intb + l * HD);
    }

    energy_kernel<<<NGRAPH, 256>>>(ow1, ob1, ow2, ob2, out);
}

// round 3
// speedup vs baseline: 1.2080x; 1.2080x over previous
#include <cuda_runtime.h>
#include <math.h>

// Problem constants (fixed by the dataset generator)
#define NATOMS 8192
#define NEDGE  262144
#define KNB    32
#define HD     128
#define NFH    128
#define NGAUSS 50
#define NGP    53          // padded edge_attr row pitch in smem
#define TPITCH 132         // padded t-transpose pitch
#define NLAY   6
#define NGRAPH 32
#define NPERG  256
#define CUTR   10.0f
#define LOG2F_ 0.69314718055994530942f
#define PI_F   3.14159265358979323846f

typedef unsigned long long u64;

// packed f32x2 fma: d = a*b + c  (elementwise on {lo,hi})
#define FMA2(d, a, b, c) \
    asm("fma.rn.f32x2 %0, %1, %2, %3;" : "=l"(d) : "l"(a), "l"(b), "l"(c))
#define PACK2(d, x) \
    do { unsigned _u = __float_as_uint(x); \
         asm("mov.b64 %0, {%1, %1};" : "=l"(d) : "r"(_u)); } while (0)
#define UNPACK2(lo, hi, p) \
    do { unsigned _a, _b; \
         asm("mov.b64 {%0, %1}, %2;" : "=r"(_a), "=r"(_b) : "l"(p)); \
         lo = __uint_as_float(_a); hi = __uint_as_float(_b); } while (0)

// ---------------- device scratch ----------------
__device__ float g_eaT[NGAUSS * NEDGE];   // gaussian smearing, TRANSPOSED [j][e]
__device__ float g_C[NEDGE];              // cosine cutoff per edge
__device__ float g_h[NATOMS * HD];        // node features
__device__ float g_X[NATOMS * NFH];       // x = h @ cf_lin1
__device__ float g_agg[NATOMS * NFH];     // aggregated messages
__device__ float g_S;                     // sum_j bias[j]

__device__ __forceinline__ float sspf(float x) {
    float e = __expf(-fabsf(x));
    return fmaxf(x, 0.0f) + __logf(1.0f + e) - LOG2F_;
}

// ---------------- trivial kernels ----------------
__global__ void __launch_bounds__(256) zero_kernel(float* __restrict__ out, int n) {
    for (int i = blockIdx.x * blockDim.x + threadIdx.x; i < n; i += gridDim.x * blockDim.x)
        out[i] = 0.0f;
}

__global__ void __launch_bounds__(256) hinit_kernel(const int* __restrict__ z,
                                                    const float* __restrict__ emb) {
    for (int i = blockIdx.x * blockDim.x + threadIdx.x; i < NATOMS * HD; i += gridDim.x * blockDim.x) {
        int n = i >> 7, f = i & 127;
        g_h[i] = emb[z[n] * HD + f];
    }
}

__global__ void __launch_bounds__(256) edge_pre_kernel(const float* __restrict__ pos,
                                                       const int* __restrict__ ei) {
    const float step  = CUTR / (float)(NGAUSS - 1);
    const float coeff = -0.5f / (step * step);
    for (int e = blockIdx.x * blockDim.x + threadIdx.x; e < NEDGE; e += gridDim.x * blockDim.x) {
        int s = ei[e], t = ei[NEDGE + e];
        float dx = pos[3 * s + 0] - pos[3 * t + 0];
        float dy = pos[3 * s + 1] - pos[3 * t + 1];
        float dz = pos[3 * s + 2] - pos[3 * t + 2];
        float d = sqrtf(dx * dx + dy * dy + dz * dz);
        g_C[e] = 0.5f * (cosf(d * (PI_F / CUTR)) + 1.0f);
#pragma unroll
        for (int j = 0; j < NGAUSS; j++) {
            float df = d - (float)j * step;
            g_eaT[j * NEDGE + e] = __expf(coeff * df * df);
        }
    }
}

// ---------------- fused filter-network + message + aggregate ----------------
// Per pass: 4 atoms = 128 contiguous edges (dst sorted, K=32).
// f32x2-packed accumulators along the f dimension.
__global__ void __launch_bounds__(256, 1) message_kernel(
    const int* __restrict__ ei,
    const float* __restrict__ w1, const float* __restrict__ b1,
    const float* __restrict__ w2, const float* __restrict__ b2)
{
    extern __shared__ float smem_dyn[];
    float* s_w1  = smem_dyn;                    // [50][128]
    float* s_b1  = s_w1 + NGAUSS * NFH;         // [128]
    float* s_w2  = s_b1 + NFH;                  // [128][128]
    float* s_b2  = s_w2 + NFH * NFH;            // [128]
    float* s_ea  = s_b2 + NFH;                  // [128][NGP]
    float* s_tT  = s_ea + 128 * NGP;            // [128][TPITCH]
    float* s_red = s_tT + 128 * TPITCH;         // [16][128]

    const int tid = threadIdx.x;
    for (int i = tid; i < NGAUSS * NFH; i += 256) s_w1[i] = w1[i];
    for (int i = tid; i < NFH * NFH;   i += 256) s_w2[i] = w2[i];
    if (tid < NFH) { s_b1[tid] = b1[tid]; s_b2[tid] = b2[tid]; }
    __syncthreads();

    const int f8 = tid & 15, eg = tid >> 4;
    const int f0 = f8 * 8,   e0 = eg * 8;

    const int ngroups = NATOMS / 4;
    for (int ag = blockIdx.x; ag < ngroups; ag += gridDim.x) {
        const int abase = ag * 4;
        const int ebase = abase * KNB;

        for (int i = tid; i < NGAUSS * 128; i += 256) {
            int j = i >> 7, el = i & 127;
            s_ea[el * NGP + j] = g_eaT[j * NEDGE + ebase + el];
        }
        __syncthreads();

        // ---- stage A: t = ssp(ea @ w1 + b1), packed over f ----
        u64 acc2[8][4];
        {
            const u64* bp = (const u64*)&s_b1[f0];
            u64 b01 = bp[0], b23 = bp[1], b45 = bp[2], b67 = bp[3];
#pragma unroll
            for (int ee = 0; ee < 8; ee++) {
                acc2[ee][0] = b01; acc2[ee][1] = b23;
                acc2[ee][2] = b45; acc2[ee][3] = b67;
            }
        }
        for (int j = 0; j < NGAUSS; j++) {
            const u64* wp = (const u64*)&s_w1[j * NFH + f0];
            u64 w0 = wp[0], w1p = wp[1], w2p = wp[2], w3p = wp[3];
#pragma unroll
            for (int ee = 0; ee < 8; ee++) {
                float ev = s_ea[(e0 + ee) * NGP + j];
                u64 evp; PACK2(evp, ev);
                FMA2(acc2[ee][0], evp, w0,  acc2[ee][0]);
                FMA2(acc2[ee][1], evp, w1p, acc2[ee][1]);
                FMA2(acc2[ee][2], evp, w2p, acc2[ee][2]);
                FMA2(acc2[ee][3], evp, w3p, acc2[ee][3]);
            }
        }
        // ssp + transposed store [f][e]
        {
            float a[8][8];
#pragma unroll
            for (int ee = 0; ee < 8; ee++)
#pragma unroll
                for (int fp = 0; fp < 4; fp++)
                    UNPACK2(a[ee][2 * fp], a[ee][2 * fp + 1], acc2[ee][fp]);
#pragma unroll
            for (int ff = 0; ff < 8; ff++) {
                float4 v0 = make_float4(sspf(a[0][ff]), sspf(a[1][ff]),
                                        sspf(a[2][ff]), sspf(a[3][ff]));
                float4 v1 = make_float4(sspf(a[4][ff]), sspf(a[5][ff]),
                                        sspf(a[6][ff]), sspf(a[7][ff]));
                *(float4*)&s_tT[(f0 + ff) * TPITCH + e0]     = v0;
                *(float4*)&s_tT[(f0 + ff) * TPITCH + e0 + 4] = v1;
            }
        }
        __syncthreads();

        // ---- stage B: W = t @ w2 + b2, packed over f ----
        {
            const u64* bp = (const u64*)&s_b2[f0];
            u64 b01 = bp[0], b23 = bp[1], b45 = bp[2], b67 = bp[3];
#pragma unroll
            for (int ee = 0; ee < 8; ee++) {
                acc2[ee][0] = b01; acc2[ee][1] = b23;
                acc2[ee][2] = b45; acc2[ee][3] = b67;
            }
        }
        for (int j = 0; j < NFH; j++) {
            const u64* wp = (const u64*)&s_w2[j * NFH + f0];
            u64 w0 = wp[0], w1p = wp[1], w2p = wp[2], w3p = wp[3];
            float4 t0 = *(const float4*)&s_tT[j * TPITCH + e0];
            float4 t1 = *(const float4*)&s_tT[j * TPITCH + e0 + 4];
            float tv[8] = {t0.x, t0.y, t0.z, t0.w, t1.x, t1.y, t1.z, t1.w};
#pragma unroll
            for (int ee = 0; ee < 8; ee++) {
                u64 tp; PACK2(tp, tv[ee]);
                FMA2(acc2[ee][0], tp, w0,  acc2[ee][0]);
                FMA2(acc2[ee][1], tp, w1p, acc2[ee][1]);
                FMA2(acc2[ee][2], tp, w2p, acc2[ee][2]);
                FMA2(acc2[ee][3], tp, w3p, acc2[ee][3]);
            }
        }

        // ---- finalize: msg = X[src] * W * C, partial-sum over 8 edges ----
        float part[8];
#pragma unroll
        for (int ff = 0; ff < 8; ff++) part[ff] = 0.0f;
#pragma unroll
        for (int ee = 0; ee < 8; ee++) {
            int e = ebase + e0 + ee;
            int s = ei[e];
            float c = g_C[e];
            float a[8];
#pragma unroll
            for (int fp = 0; fp < 4; fp++) UNPACK2(a[2 * fp], a[2 * fp + 1], acc2[ee][fp]);
            float4 x0 = *(const float4*)&g_X[s * NFH + f0];
            float4 x1 = *(const float4*)&g_X[s * NFH + f0 + 4];
            part[0] += x0.x * (a[0] * c); part[1] += x0.y * (a[1] * c);
            part[2] += x0.z * (a[2] * c); part[3] += x0.w * (a[3] * c);
            part[4] += x1.x * (a[4] * c); part[5] += x1.y * (a[5] * c);
            part[6] += x1.z * (a[6] * c); part[7] += x1.w * (a[7] * c);
        }
#pragma unroll
        for (int ff = 0; ff < 8; ff++) s_red[eg * NFH + f0 + ff] = part[ff];
        __syncthreads();

        for (int i = tid; i < 4 * NFH; i += 256) {
            int a = i >> 7, f = i & 127;
            float v = s_red[(a * 4 + 0) * NFH + f] + s_red[(a * 4 + 1) * NFH + f] +
                      s_red[(a * 4 + 2) * NFH + f] + s_red[(a * 4 + 3) * NFH + f];
            g_agg[(abase + a) * NFH + f] = v;
        }
        __syncthreads();
    }
}

// ---------------- generic 128x128 node GEMM (f32x2) ----------------
template <int MODE>
__global__ void __launch_bounds__(256, 1) gemm_kernel(
    const float* __restrict__ W, const float* __restrict__ bias)
{
    extern __shared__ float smem_dyn[];
    float* s_w = smem_dyn;
    float* s_x = s_w + NFH * NFH;
    float* s_b = s_x + 64 * 132;

    const float* Xin = (MODE == 0) ? g_h : (MODE == 1) ? g_agg : g_X;
    float* Y         = (MODE == 2) ? g_h : g_X;

    const int tid = threadIdx.x;
    for (int i = tid; i < NFH * NFH; i += 256) s_w[i] = W[i];
    if (tid < NFH) s_b[tid] = (MODE == 0) ? 0.0f : bias[tid];
    __syncthreads();

    const int f8 = tid & 15, aq = tid >> 4;
    const int f0 = f8 * 8,   a0 = aq * 4;

    for (int blk = blockIdx.x; blk < NATOMS / 64; blk += gridDim.x) {
        int abase = blk * 64;
        for (int i = tid; i < 64 * NFH; i += 256) {
            int a = i >> 7, f = i & 127;
            s_x[a * 132 + f] = Xin[(abase + a) * NFH + f];
        }
        __syncthreads();

        u64 acc2[4][4];
        {
            const u64* bp = (const u64*)&s_b[f0];
            u64 b01 = bp[0], b23 = bp[1], b45 = bp[2], b67 = bp[3];
#pragma unroll
            for (int aa = 0; aa < 4; aa++) {
                acc2[aa][0] = b01; acc2[aa][1] = b23;
                acc2[aa][2] = b45; acc2[aa][3] = b67;
            }
        }
        for (int j = 0; j < NFH; j++) {
            const u64* wp = (const u64*)&s_w[j * NFH + f0];
            u64 w0 = wp[0], w1p = wp[1], w2p = wp[2], w3p = wp[3];
#pragma unroll
            for (int aa = 0; aa < 4; aa++) {
                float xv = s_x[(a0 + aa) * 132 + j];
                u64 xp; PACK2(xp, xv);
                FMA2(acc2[aa][0], xp, w0,  acc2[aa][0]);
                FMA2(acc2[aa][1], xp, w1p, acc2[aa][1]);
                FMA2(acc2[aa][2], xp, w2p, acc2[aa][2]);
                FMA2(acc2[aa][3], xp, w3p, acc2[aa][3]);
            }
        }
#pragma unroll
        for (int aa = 0; aa < 4; aa++) {
            float a[8];
#pragma unroll
            for (int fp = 0; fp < 4; fp++) UNPACK2(a[2 * fp], a[2 * fp + 1], acc2[aa][fp]);
            int row = (abase + a0 + aa) * NFH + f0;
            float4 r0, r1;
            if (MODE == 1) {
                r0 = make_float4(sspf(a[0]), sspf(a[1]), sspf(a[2]), sspf(a[3]));
                r1 = make_float4(sspf(a[4]), sspf(a[5]), sspf(a[6]), sspf(a[7]));
            } else if (MODE == 2) {
                float4 y0 = *(const float4*)&Y[row];
                float4 y1 = *(const float4*)&Y[row + 4];
                r0 = make_float4(y0.x + a[0], y0.y + a[1], y0.z + a[2], y0.w + a[3]);
                r1 = make_float4(y1.x + a[4], y1.y + a[5], y1.z + a[6], y1.w + a[7]);
            } else {
                r0 = make_float4(a[0], a[1], a[2], a[3]);
                r1 = make_float4(a[4], a[5], a[6], a[7]);
            }
            *(float4*)&Y[row]     = r0;
            *(float4*)&Y[row + 4] = r1;
        }
        __syncthreads();
    }
}

// ---------------- FiLM bias, algebraically collapsed ----------------
// S = sum_g f1[g].u + 32*(c2 + bbs)
//   v[k]  = sum_h bw[k][h];  u[j] = sum_k fw2[j][k] v[k]
//   c2    = sum_k fb2[k] v[k];  bbs = sum_h bb[h]
//   f1[g] = relu(de[g] @ fw1 + fb1)
__global__ void __launch_bounds__(256) bias_kernel(
    const int* __restrict__ dom_ids, const float* __restrict__ dom_emb,
    const float* __restrict__ fw1, const float* __restrict__ fb1,
    const float* __restrict__ fw2, const float* __restrict__ fb2,
    const float* __restrict__ bw,  const float* __restrict__ bb)
{
    __shared__ float s_v[128];
    __shared__ float s_u[128];
    __shared__ float s_de[NGRAPH * 64];
    __shared__ float s_red[8];
    int tid = threadIdx.x;

    if (tid < 128) {
        float s = 0.0f;
        for (int h = 0; h < 128; h++) s += bw[tid * 128 + h];
        s_v[tid] = s;
    }
    for (int i = tid; i < NGRAPH * 64; i += 256) {
        int g = i >> 6, k = i & 63;
        s_de[i] = dom_emb[dom_ids[g] * 64 + k];
    }
    __syncthreads();
    if (tid < 128) {
        float s = 0.0f;
        for (int k = 0; k < 128; k++) s += fw2[tid * 128 + k] * s_v[k];
        s_u[tid] = s;
    }
    __syncthreads();

    float sl = 0.0f;
    if (tid < 128) sl += (float)NGRAPH * (fb2[tid] * s_v[tid] + bb[tid]);
    for (int idx = tid; idx < NGRAPH * 128; idx += 256) {
        int g = idx >> 7, j = idx & 127;
        float a = fb1[j];
        for (int i = 0; i < 64; i++) a += s_de[g * 64 + i] * fw1[i * 128 + j];
        sl += fmaxf(a, 0.0f) * s_u[j];
    }
    for (int o = 16; o; o >>= 1) sl += __shfl_xor_sync(0xffffffffu, sl, o);
    if ((tid & 31) == 0) s_red[tid >> 5] = sl;
    __syncthreads();
    if (tid == 0) {
        float v = 0.0f;
        for (int w = 0; w < 8; w++) v += s_red[w];
        g_S = v;
    }
}

// ---------------- output head ----------------
__global__ void __launch_bounds__(256) energy_kernel(
    const float* __restrict__ w1, const float* __restrict__ b1,
    const float* __restrict__ w2, const float* __restrict__ b2,
    float* __restrict__ out)
{
    __shared__ float s_w1[HD * 64];
    __shared__ float s_w2[64];
    __shared__ float s_red[8];
    int tid = threadIdx.x;
    for (int i = tid; i < HD * 64; i += 256) s_w1[i] = w1[i];
    if (tid < 64) s_w2[tid] = w2[tid];
    __syncthreads();

    int atom = blockIdx.x * NPERG + tid;
    float e = b2[0];
#pragma unroll
    for (int half = 0; half < 2; half++) {
        float u[32];
#pragma unroll
        for (int f = 0; f < 32; f++) u[f] = b1[half * 32 + f];
        for (int j = 0; j < HD; j++) {
            float hv = g_h[atom * HD + j];
#pragma unroll
            for (int f = 0; f < 32; f++) u[f] += hv * s_w1[j * 64 + half * 32 + f];
        }
#pragma unroll
        for (int f = 0; f < 32; f++) e += sspf(u[f]) * s_w2[half * 32 + f];
    }

    for (int o = 16; o; o >>= 1) e += __shfl_xor_sync(0xffffffffu, e, o);
    if ((tid & 31) == 0) s_red[tid >> 5] = e;
    __syncthreads();
    if (tid == 0) {
        float tot = 0.0f;
        for (int w = 0; w < 8; w++) tot += s_red[w];
        out[blockIdx.x] = (float)NGRAPH * tot + g_S;
    }
}

// ---------------- launch ----------------
extern "C" void kernel_launch(void* const* d_in, const int* in_sizes, int n_in,
                              void* d_out, int out_size)
{
    const float* pos    = (const float*)d_in[0];
    const int*   z      = (const int*)  d_in[1];
    const int*   ei     = (const int*)  d_in[3];
    const int*   dom    = (const int*)  d_in[4];
    const float* emb    = (const float*)d_in[5];
    const float* mlp_w1 = (const float*)d_in[6];
    const float* mlp_b1 = (const float*)d_in[7];
    const float* mlp_w2 = (const float*)d_in[8];
    const float* mlp_b2 = (const float*)d_in[9];
    const float* cf1    = (const float*)d_in[10];
    const float* cf2    = (const float*)d_in[11];
    const float* cf2b   = (const float*)d_in[12];
    const float* intw   = (const float*)d_in[13];
    const float* intb   = (const float*)d_in[14];
    const float* ow1    = (const float*)d_in[15];
    const float* ob1    = (const float*)d_in[16];
    const float* ow2    = (const float*)d_in[17];
    const float* ob2    = (const float*)d_in[18];
    const float* dome   = (const float*)d_in[19];
    const float* fw1    = (const float*)d_in[20];
    const float* fb1    = (const float*)d_in[21];
    const float* fw2    = (const float*)d_in[22];
    const float* fb2    = (const float*)d_in[23];
    const float* bw     = (const float*)d_in[26];
    const float* bb     = (const float*)d_in[27];
    float* out = (float*)d_out;

    const int MSG_SMEM  = (NGAUSS * NFH + NFH + NFH * NFH + NFH +
                           128 * NGP + 128 * TPITCH + 16 * NFH) * (int)sizeof(float);
    const int GEMM_SMEM = (NFH * NFH + 64 * 132 + NFH) * (int)sizeof(float);

    cudaFuncSetAttribute(message_kernel, cudaFuncAttributeMaxDynamicSharedMemorySize, MSG_SMEM);
    cudaFuncSetAttribute(gemm_kernel<0>, cudaFuncAttributeMaxDynamicSharedMemorySize, GEMM_SMEM);
    cudaFuncSetAttribute(gemm_kernel<1>, cudaFuncAttributeMaxDynamicSharedMemorySize, GEMM_SMEM);
    cudaFuncSetAttribute(gemm_kernel<2>, cudaFuncAttributeMaxDynamicSharedMemorySize, GEMM_SMEM);

    zero_kernel<<<512, 256>>>(out, out_size);
    edge_pre_kernel<<<1024, 256>>>(pos, ei);
    hinit_kernel<<<512, 256>>>(z, emb);
    bias_kernel<<<1, 256>>>(dom, dome, fw1, fb1, fw2, fb2, bw, bb);

    for (int l = 0; l < NLAY; l++) {
        gemm_kernel<0><<<128, 256, GEMM_SMEM>>>(cf1 + l * HD * NFH, nullptr);
        message_kernel<<<148, 256, MSG_SMEM>>>(ei,
            mlp_w1 + l * NGAUSS * NFH, mlp_b1 + l * NFH,
            mlp_w2 + l * NFH * NFH,    mlp_b2 + l * NFH);
        gemm_kernel<1><<<128, 256, GEMM_SMEM>>>(cf2 + l * NFH * HD, cf2b + l * HD);
        gemm_kernel<2><<<128, 256, GEMM_SMEM>>>(intw + l * HD * HD, intb + l * HD);
    }

    energy_kernel<<<NGRAPH, 256>>>(ow1, ob1, ow2, ob2, out);
}